// round 10
// baseline (speedup 1.0000x reference)
#include <cuda_runtime.h>

#define Bn 64
#define Tn 512
#define Ln 48
#define HALF 256
#define STARTL 46
#define ENDL 47
#define PFD 4
#define NCTA (3*Bn)
#define LOG2E_F 1.4426950408889634f
#define LN2_F   0.6931471805599453f

__device__ __forceinline__ float ex2f_(float x){float r;asm("ex2.approx.f32 %0,%1;":"=f"(r):"f"(x));return r;}
__device__ __forceinline__ float lg2f_(float x){float r;asm("lg2.approx.f32 %0,%1;":"=f"(r):"f"(x));return r;}
__device__ __forceinline__ unsigned long long pack2_(float a,float b){
    unsigned long long d;asm("mov.b64 %0,{%1,%2};":"=l"(d):"f"(a),"f"(b));return d;}
__device__ __forceinline__ void unpack2_(unsigned long long d,float&a,float&b){
    asm("mov.b64 {%0,%1},%2;":"=f"(a),"=f"(b):"l"(d));}
__device__ __forceinline__ void fma2_(unsigned long long&d,unsigned long long a,unsigned long long b){
    asm("fma.rn.f32x2 %0,%1,%2,%0;":"+l"(d):"l"(a),"l"(b));}
__device__ __forceinline__ unsigned long long mul2_(unsigned long long a,unsigned long long b){
    unsigned long long d;asm("mul.rn.f32x2 %0,%1,%2;":"=l"(d):"l"(a),"l"(b));return d;}
__device__ __forceinline__ unsigned long long add2_(unsigned long long a,unsigned long long b){
    unsigned long long d;asm("add.rn.f32x2 %0,%1,%2;":"=l"(d):"l"(a),"l"(b));return d;}

// cross-CTA scratch
__device__ float g_scr[2][Bn][64];   // [dir][batch][48 used]
__device__ int   c_scr[2][Bn];       // exponent accumulators
__device__ float e_scr[Bn];          // gold-path energy per batch
__device__ int   done_ctr = 0;       // last-block-done counter (reset by last block)

// shared matvec body: v (12 x ulonglong2 from smem) dot per-thread w[24] -> GPOUT
#define MATVEC(GPOUT) \
    unsigned long long a0 = mul2_(v[0].x, w[0]);                               \
    unsigned long long a1 = mul2_(v[0].y, w[1]);                               \
    unsigned long long a2 = mul2_(v[1].x, w[2]);                               \
    unsigned long long a3 = mul2_(v[1].y, w[3]);                               \
    _Pragma("unroll") for (int p = 4; p < 24; p += 4){                         \
        fma2_(a0, v[(p>>1)    ].x, w[p  ]);                                    \
        fma2_(a1, v[(p>>1)    ].y, w[p+1]);                                    \
        fma2_(a2, v[(p>>1) + 1].x, w[p+2]);                                    \
        fma2_(a3, v[(p>>1) + 1].y, w[p+3]);                                    \
    }                                                                          \
    unsigned long long s01_ = add2_(a0, a1);                                   \
    unsigned long long s23_ = add2_(a2, a3);                                   \
    unsigned long long sal_ = add2_(s01_, s23_);                               \
    float lo_, hi_; unpack2_(sal_, lo_, hi_);                                  \
    float GPOUT = lo_ + hi_;

// forward step: h' = select(W^T h, g_prev) * scale * e_{t+1}
#define STEPF(T_, CUR, NXT, PFV) do {                                          \
    const ulonglong2* hp_ = (const ulonglong2*)(h_sh + (CUR));                 \
    ulonglong2 v[12];                                                          \
    _Pragma("unroll") for (int j = 0; j < 12; j++) v[j] = hp_[j];              \
    const int m_t_ = m_sh[T_];                                                 \
    float e_ = ex2f_((PFV) * LOG2E_F);                                         \
    PFV = sp[((T_) + 1 + PFD) * Ln];                                           \
    float h0_, hxx_; unpack2_(v[0].x, h0_, hxx_);                              \
    unsigned ue_ = __float_as_uint(h0_) >> 23;                                 \
    C2i += (int)ue_;                                                           \
    float scale_ = __uint_as_float((254u - ue_) << 23);                        \
    float se_ = scale_ * e_;                                                   \
    MATVEC(gp_)                                                                \
    float gsel_ = m_t_ ? gp_ : g_prev;                                         \
    g_prev = gsel_ * scale_;                                                   \
    if (tid < Ln) h_sh[(NXT) + tid] = gsel_ * se_;                             \
    __syncthreads();                                                           \
} while(0)

// backward step: beta' = select((W beta) * e_t, beta_old) * scale
#define STEPB(T_, CUR, NXT, PFV) do {                                          \
    const ulonglong2* hp_ = (const ulonglong2*)(h_sh + (CUR));                 \
    ulonglong2 v[12];                                                          \
    _Pragma("unroll") for (int j = 0; j < 12; j++) v[j] = hp_[j];              \
    const int m_t_ = m_sh[T_];                                                 \
    float e_ = ex2f_((PFV) * LOG2E_F);                                         \
    PFV = sp[((T_) - PFD) * Ln];                                               \
    float h0_, hxx_; unpack2_(v[0].x, h0_, hxx_);                              \
    unsigned ue_ = __float_as_uint(h0_) >> 23;                                 \
    C2i += (int)ue_;                                                           \
    float scale_ = __uint_as_float((254u - ue_) << 23);                        \
    MATVEC(gp_)                                                                \
    float cand_ = gp_ * e_;                                                    \
    float bsel_ = m_t_ ? cand_ : bp;                                           \
    bp = bsel_ * scale_;                                                       \
    if (tid < Ln) h_sh[(NXT) + tid] = bp;                                      \
    __syncthreads();                                                           \
} while(0)

__global__ __launch_bounds__(64,1)
void crf_fused(const float* __restrict__ scores,
               const int*   __restrict__ gold_i,   // int32 view (may really be int64)
               const int*   __restrict__ mask,
               const float* __restrict__ trans,
               float*       __restrict__ out)
{
    __shared__ float h_sh[2*Ln];
    __shared__ int   m_sh[Tn];
    __shared__ float ps[64];
    __shared__ int   flag_sh[1];

    const int tid = threadIdx.x;
    const int bx  = blockIdx.x;
    const int b   = bx & (Bn-1);
    const int dir = bx >> 6;          // 0=fwd, 1=bwd, 2=gold

    const int yy = (tid < Ln) ? tid : 0;
    const float* sp = scores + (size_t)b * Tn * Ln + yy;

    if (dir == 0) {
        {   // stage mask row (2 KB)
            const int4* msrc = (const int4*)(mask + b * Tn);
            #pragma unroll
            for (int i = tid; i < Tn/4; i += 64) ((int4*)m_sh)[i] = msrc[i];
        }
        // w = column yy of W = exp(trans)
        unsigned long long w[24];
        #pragma unroll
        for (int j = 0; j < 24; j++){
            float wa = ex2f_(trans[(2*j  )*Ln + yy] * LOG2E_F);
            float wb = ex2f_(trans[(2*j+1)*Ln + yy] * LOG2E_F);
            w[j] = pack2_(wa, wb);
        }
        float pf0 = sp[1*Ln], pf1 = sp[2*Ln], pf2 = sp[3*Ln], pf3 = sp[4*Ln];
        float ts = trans[STARTL*Ln + yy];
        float g_prev = ex2f_(ts * LOG2E_F);
        if (tid < Ln) h_sh[tid] = ex2f_((ts + sp[0]) * LOG2E_F);
        __syncthreads();

        int C2i = 0;
        for (int t = 0; t < HALF; t += 4){
            STEPF(t  , 0,  Ln, pf0);
            STEPF(t+1, Ln, 0,  pf1);
            STEPF(t+2, 0,  Ln, pf2);
            STEPF(t+3, Ln, 0,  pf3);
        }
        if (tid < Ln) g_scr[0][b][tid] = g_prev;
        if (tid == 0) c_scr[0][b] = C2i;
    } else if (dir == 1) {
        {   // stage mask row (2 KB)
            const int4* msrc = (const int4*)(mask + b * Tn);
            #pragma unroll
            for (int i = tid; i < Tn/4; i += 64) ((int4*)m_sh)[i] = msrc[i];
        }
        // w = row yy of W
        unsigned long long w[24];
        #pragma unroll
        for (int j = 0; j < 24; j++){
            float wa = ex2f_(trans[yy*Ln + 2*j    ] * LOG2E_F);
            float wb = ex2f_(trans[yy*Ln + 2*j + 1] * LOG2E_F);
            w[j] = pack2_(wa, wb);
        }
        float pf0 = sp[511*Ln], pf1 = sp[510*Ln], pf2 = sp[509*Ln], pf3 = sp[508*Ln];
        // beta_512 = delta_END * 2^-64 (bias compensated by +64 in combine)
        float bp = (yy == ENDL) ? 0x1p-64f : 0.0f;
        if (tid < Ln) h_sh[tid] = bp;
        __syncthreads();

        int C2i = 0;
        for (int t = Tn-1; t >= HALF+3; t -= 4){
            STEPB(t  , 0,  Ln, pf0);
            STEPB(t-1, Ln, 0,  pf1);
            STEPB(t-2, 0,  Ln, pf2);
            STEPB(t-3, Ln, 0,  pf3);
        }
        if (tid < Ln) g_scr[1][b][tid] = bp;
        if (tid == 0) c_scr[1][b] = C2i;
    } else {
        // ---- gold-path energy: sum_t mask * (scores[b,t,0] + trans[0, gold[b,t]]) ----
        float* t0_sh = (float*)m_sh;            // reuse smem
        if (tid < Ln) t0_sh[tid] = trans[tid];  // trans row 0
        if (tid == 0){                          // gold dtype detect (int64 hi-words zero)
            int f = 1;
            #pragma unroll
            for (int j = 0; j < 32; j++) f &= (gold_i[2*j+1] == 0);
            flag_sh[0] = f;
        }
        __syncthreads();
        const int is64 = flag_sh[0];
        const float* sb0 = scores + (size_t)b * Tn * Ln;
        const int*   mb  = mask + b * Tn;
        float p = 0.0f;
        #pragma unroll 4
        for (int tt = tid; tt < Tn; tt += 64){
            int idx = b*Tn + tt;
            int g   = is64 ? gold_i[2*idx] : gold_i[idx];
            p += (float)mb[tt] * (sb0[tt*Ln] + t0_sh[g]);
        }
        ps[tid] = p;
        __syncthreads();
        if (tid == 0){
            float tot = 0.0f;
            #pragma unroll
            for (int i = 0; i < 64; i++) tot += ps[i];
            e_scr[b] = tot;
        }
    }

    // ---- last-CTA combine ----
    __syncthreads();
    if (tid == 0){
        __threadfence();
        int prev = atomicAdd(&done_ctr, 1);
        flag_sh[0] = (prev == NCTA - 1);
    }
    __syncthreads();
    if (!flag_sh[0]) return;
    __threadfence();

    // each thread handles one batch
    {
        const int bb = tid;
        float Z = 0.0f;
        const float* gf = g_scr[0][bb];
        const float* gb = g_scr[1][bb];
        #pragma unroll
        for (int i = 0; i < Ln; i++) Z += gf[i] * gb[i];
        int bias = c_scr[0][bb] + c_scr[1][bb] - 127*Tn + 64;
        float fsend = ((float)bias + lg2f_(Z)) * LN2_F;
        ps[tid] = fsend - e_scr[bb];
    }
    __syncthreads();
    if (tid == 0){
        float acc = 0.0f;
        #pragma unroll
        for (int i = 0; i < 64; i++) acc += ps[i];
        float tStart = trans[STARTL];   // trans[0][START]
        out[0] = (acc - (float)Bn * tStart) * (1.0f / (float)Bn);
        __threadfence();
        done_ctr = 0;                   // reset for next graph replay
    }
}

extern "C" void kernel_launch(void* const* d_in, const int* in_sizes, int n_in,
                              void* d_out, int out_size)
{
    const float* scores = (const float*)d_in[0];
    const int*   gold   = (const int*)  d_in[1];
    const int*   mask   = (const int*)  d_in[2];
    const float* trans  = (const float*)d_in[3];
    float* out = (float*)d_out;

    crf_fused<<<NCTA, 64>>>(scores, gold, mask, trans, out);
}